// round 15
// baseline (speedup 1.0000x reference)
#include <cuda_runtime.h>
#include <cuda_bf16.h>
#include <cuda_fp16.h>
#include <cstdint>

#define N_NODES 50000
#define N_EDGES 600000
#define FEAT    128
#define N_CLS   40
#define NTILES  782          // ceil(50000/64)

// ---------------- scratch (no allocations allowed) ----------------
__device__ float  g_dinv[N_NODES];
__device__ int    g_degi[N_NODES];
__device__ int    g_rowptr[N_NODES];
__device__ int    g_cursor[N_NODES];
__device__ int    g_esrc[N_EDGES];
__device__ float  g_agg[N_NODES * FEAT];
__device__ float  g_h1[N_NODES * FEAT];
__device__ float  g_h2[N_NODES * FEAT];
__device__ float  g_h3[N_NODES * FEAT];
__device__ __half g_h16[N_NODES * FEAT];   // fp16 shadow of the gather input
// pre-split weights: 6 x [hi 16384 | lo 16384], then Wc [hi 5120 | lo 5120]
#define WC_OFF (6 * 32768)
__device__ __nv_bfloat16 g_wsplit[6 * 32768 + 2 * 5120];

// ---------------- PTX helpers ----------------
__device__ __forceinline__ uint32_t smem_u32(const void* p) {
    uint32_t a;
    asm("{ .reg .u64 t; cvta.to.shared.u64 t, %1; cvt.u32.u64 %0, t; }" : "=r"(a) : "l"(p));
    return a;
}

__device__ __forceinline__ void mma_bf16(float* c, const uint32_t* a, uint32_t b0, uint32_t b1) {
    asm volatile(
        "mma.sync.aligned.m16n8k16.row.col.f32.bf16.bf16.f32 "
        "{%0,%1,%2,%3}, {%4,%5,%6,%7}, {%8,%9}, {%0,%1,%2,%3};"
        : "+f"(c[0]), "+f"(c[1]), "+f"(c[2]), "+f"(c[3])
        : "r"(a[0]), "r"(a[1]), "r"(a[2]), "r"(a[3]), "r"(b0), "r"(b1));
}

#define LDMX4(R, addr) \
    asm volatile("ldmatrix.sync.aligned.m8n8.x4.shared.b16 {%0,%1,%2,%3}, [%4];" \
        : "=r"((R)[0]), "=r"((R)[1]), "=r"((R)[2]), "=r"((R)[3]) : "r"(addr))
#define LDMX2(R, addr) \
    asm volatile("ldmatrix.sync.aligned.m8n8.x2.shared.b16 {%0,%1}, [%2];" \
        : "=r"((R)[0]), "=r"((R)[1]) : "r"(addr))

#define LDS_STRIDE 136   // 272B rows (17 x 16B, odd -> ldmatrix conflict-free)

__device__ __forceinline__ void split2(float f0, float f1, uint32_t& hw, uint32_t& lw) {
    __nv_bfloat16 h0 = __float2bfloat16(f0);
    __nv_bfloat16 h1 = __float2bfloat16(f1);
    __nv_bfloat16 l0 = __float2bfloat16(f0 - __bfloat162float(h0));
    __nv_bfloat16 l1 = __float2bfloat16(f1 - __bfloat162float(h1));
    hw = ((uint32_t)__bfloat16_as_ushort(h1) << 16) | __bfloat16_as_ushort(h0);
    lw = ((uint32_t)__bfloat16_as_ushort(l1) << 16) | __bfloat16_as_ushort(l0);
}

// ---------------- prep: weight split + Wc + zero degi + x->fp16 (one grid) ----------------
// blocks [0,384): 6 W mats; [384,404): Wc; [404,600): zero degi; [600,6850): x -> h16
__global__ void prep_and_zero(const float* __restrict__ Wl1, const float* __restrict__ Wr1,
                              const float* __restrict__ Wl2, const float* __restrict__ Wr2,
                              const float* __restrict__ Wl3, const float* __restrict__ Wr3,
                              const float* __restrict__ Wc, const float* __restrict__ x) {
    int b = blockIdx.x;
    if (b < 384) {
        int idx = b * 256 + threadIdx.x;
        int lm = idx / 16384;
        int e  = idx % 16384;
        const float* W;
        switch (lm) {
            case 0: W = Wl1; break;
            case 1: W = Wr1; break;
            case 2: W = Wl2; break;
            case 3: W = Wr2; break;
            case 4: W = Wl3; break;
            default: W = Wr3; break;
        }
        float f = __ldg(W + e);
        __nv_bfloat16 h = __float2bfloat16(f);
        __nv_bfloat16 l = __float2bfloat16(f - __bfloat162float(h));
        __nv_bfloat16* base = g_wsplit + (size_t)lm * 32768;
        base[e]         = h;
        base[16384 + e] = l;
    } else if (b < 404) {
        int e = (b - 384) * 256 + threadIdx.x;
        if (e < 5120) {
            float f = __ldg(Wc + e);
            __nv_bfloat16 h = __float2bfloat16(f);
            __nv_bfloat16 l = __float2bfloat16(f - __bfloat162float(h));
            g_wsplit[WC_OFF + e]        = h;
            g_wsplit[WC_OFF + 5120 + e] = l;
        }
    } else if (b < 600) {
        int i = (b - 404) * 256 + threadIdx.x;
        if (i < N_NODES) g_degi[i] = 0;
    } else {
        int i = ((b - 600) * 256 + threadIdx.x) * 4;   // covers 6.4M exactly
        float4 v = __ldg(reinterpret_cast<const float4*>(x + i));
        __half2 h0 = __floats2half2_rn(v.x, v.y);
        __half2 h1 = __floats2half2_rn(v.z, v.w);
        *reinterpret_cast<uint2*>(g_h16 + i) =
            make_uint2(*reinterpret_cast<uint32_t*>(&h0), *reinterpret_cast<uint32_t*>(&h1));
    }
}

// ---------------- degree count ----------------
__global__ void deg_count_i(const int* __restrict__ dst) {
    int e = blockIdx.x * blockDim.x + threadIdx.x;
    if (e < N_EDGES) atomicAdd(&g_degi[dst[e]], 1);
}

// ---------------- single-kernel scan via smem staging ----------------
#define SCAN_R     1568
#define SMEM_SCAN  (32 * SCAN_R * 4)

__global__ __launch_bounds__(1024)
void scan_all() {
    extern __shared__ int sdeg[];
    __shared__ int woff[32];
    const int t = threadIdx.x, lane = t & 31, w = t >> 5;
    const int base = w * SCAN_R;

    for (int i = t; i < 32 * SCAN_R; i += 1024)
        sdeg[i] = (i < N_NODES) ? g_degi[i] : 0;
    __syncthreads();

    int sum = 0;
    for (int i = lane; i < SCAN_R; i += 32) sum += sdeg[base + i];
#pragma unroll
    for (int d = 16; d; d >>= 1) sum += __shfl_down_sync(0xffffffffu, sum, d);
    if (lane == 0) woff[w] = sum;
    __syncthreads();
    if (w == 0) {
        int v = woff[lane];
        int inc = v;
#pragma unroll
        for (int d = 1; d < 32; d <<= 1) {
            int u = __shfl_up_sync(0xffffffffu, inc, d);
            if (lane >= d) inc += u;
        }
        woff[lane] = inc - v;
    }
    __syncthreads();

    int run = woff[w];
    for (int c = 0; c < SCAN_R; c += 32) {
        int idx = base + c + lane;
        int v = sdeg[idx];
        int inc = v;
#pragma unroll
        for (int d = 1; d < 32; d <<= 1) {
            int u = __shfl_up_sync(0xffffffffu, inc, d);
            if (lane >= d) inc += u;
        }
        if (idx < N_NODES) {
            int excl = run + inc - v;
            g_rowptr[idx] = excl;
            g_cursor[idx] = excl;
            g_dinv[idx]   = 1.0f / fmaxf((float)v, 1.0f);
        }
        run += __shfl_sync(0xffffffffu, inc, 31);
    }
}

__global__ void bucket_edges(const int* __restrict__ src, const int* __restrict__ dst) {
    int e = blockIdx.x * blockDim.x + threadIdx.x;
    if (e < N_EDGES) {
        int d = dst[e];
        int pos = atomicAdd(&g_cursor[d], 1);
        g_esrc[pos] = src[e];
    }
}

// ---------------- CSR mean-gather (fp16 rows, 2 edges per LDG instruction) ----------------
// One warp per node. Row = 128 fp16 = 256B = 16 lanes x 16B.
// Half-warp 0 (lanes 0-15) takes even edges, half-warp 1 takes odd edges;
// each LDG.128 instruction therefore covers TWO edges. shfl_xor(16) combines.
__global__ __launch_bounds__(256)
void gather_mean(const __half* __restrict__ X16) {
    int node = (blockIdx.x * blockDim.x + threadIdx.x) >> 5;
    int lane = threadIdx.x & 31;
    if (node >= N_NODES) return;
    const int half = lane >> 4;       // 0 or 1
    const int cl   = lane & 15;       // 16B chunk within row
    int start = __ldg(g_rowptr + node);
    int deg   = __ldg(g_degi + node);

    float4 a0 = make_float4(0.f, 0.f, 0.f, 0.f);
    float4 a1 = a0;

    const int cnt = (deg - half + 1) >> 1;   // edges for this half (indices 2k+half)
    int k = 0;
    for (; k + 4 <= cnt; k += 4) {
        int e0 = start + 2 * k + half;
        int s0 = __ldg(g_esrc + e0);
        int s1 = __ldg(g_esrc + e0 + 2);
        int s2 = __ldg(g_esrc + e0 + 4);
        int s3 = __ldg(g_esrc + e0 + 6);
        uint4 q0 = __ldg(reinterpret_cast<const uint4*>(X16 + (size_t)s0 * FEAT) + cl);
        uint4 q1 = __ldg(reinterpret_cast<const uint4*>(X16 + (size_t)s1 * FEAT) + cl);
        uint4 q2 = __ldg(reinterpret_cast<const uint4*>(X16 + (size_t)s2 * FEAT) + cl);
        uint4 q3 = __ldg(reinterpret_cast<const uint4*>(X16 + (size_t)s3 * FEAT) + cl);
#pragma unroll
        for (int q = 0; q < 4; q++) {
            uint4 qq = (q == 0) ? q0 : (q == 1) ? q1 : (q == 2) ? q2 : q3;
            float2 f0 = __half22float2(*reinterpret_cast<__half2*>(&qq.x));
            float2 f1 = __half22float2(*reinterpret_cast<__half2*>(&qq.y));
            float2 f2 = __half22float2(*reinterpret_cast<__half2*>(&qq.z));
            float2 f3 = __half22float2(*reinterpret_cast<__half2*>(&qq.w));
            a0.x += f0.x; a0.y += f0.y; a0.z += f1.x; a0.w += f1.y;
            a1.x += f2.x; a1.y += f2.y; a1.z += f3.x; a1.w += f3.y;
        }
    }
    for (; k < cnt; k++) {
        int s = __ldg(g_esrc + start + 2 * k + half);
        uint4 qq = __ldg(reinterpret_cast<const uint4*>(X16 + (size_t)s * FEAT) + cl);
        float2 f0 = __half22float2(*reinterpret_cast<__half2*>(&qq.x));
        float2 f1 = __half22float2(*reinterpret_cast<__half2*>(&qq.y));
        float2 f2 = __half22float2(*reinterpret_cast<__half2*>(&qq.z));
        float2 f3 = __half22float2(*reinterpret_cast<__half2*>(&qq.w));
        a0.x += f0.x; a0.y += f0.y; a0.z += f1.x; a0.w += f1.y;
        a1.x += f2.x; a1.y += f2.y; a1.z += f3.x; a1.w += f3.y;
    }

    // combine the two halves (lane L <-> lane L^16 hold the same chunk)
    a0.x += __shfl_xor_sync(0xffffffffu, a0.x, 16);
    a0.y += __shfl_xor_sync(0xffffffffu, a0.y, 16);
    a0.z += __shfl_xor_sync(0xffffffffu, a0.z, 16);
    a0.w += __shfl_xor_sync(0xffffffffu, a0.w, 16);
    a1.x += __shfl_xor_sync(0xffffffffu, a1.x, 16);
    a1.y += __shfl_xor_sync(0xffffffffu, a1.y, 16);
    a1.z += __shfl_xor_sync(0xffffffffu, a1.z, 16);
    a1.w += __shfl_xor_sync(0xffffffffu, a1.w, 16);

    float di = __ldg(g_dinv + node);
    a0.x *= di; a0.y *= di; a0.z *= di; a0.w *= di;
    a1.x *= di; a1.y *= di; a1.z *= di; a1.w *= di;

    // half 0 writes floats [cl*8, cl*8+4), half 1 writes [cl*8+4, cl*8+8)
    float4* dst = reinterpret_cast<float4*>(g_agg + (size_t)node * FEAT + cl * 8) + half;
    *dst = half ? a1 : a0;
}

// ---------------- persistent SAGE GEMM (R10: 256 threads, 8 warps 2Mx4N) ----------------
#define W_PLANE_B  34816
#define A_PLANE_B  17408
#define A_BASE_B   139264
#define SMEM_PERS  208896

__device__ __forceinline__ void ldg_tile(const float* __restrict__ A, int m0, int tid,
                                         float4* sv) {
#pragma unroll
    for (int k = 0; k < 4; k++) {
        int it = tid + (k << 8);
        int r = it >> 4, c = it & 15;
        int m = m0 + r;
        float4 z = make_float4(0.f, 0.f, 0.f, 0.f);
        if (m < N_NODES) {
            const float4* gp = reinterpret_cast<const float4*>(A + (size_t)m * FEAT + c * 8);
            sv[2 * k]     = __ldg(gp);
            sv[2 * k + 1] = __ldg(gp + 1);
        } else {
            sv[2 * k] = z;
            sv[2 * k + 1] = z;
        }
    }
}

__device__ __forceinline__ void sts_tile(__nv_bfloat16* __restrict__ sAh,
                                         __nv_bfloat16* __restrict__ sAl,
                                         int tid, const float4* sv) {
#pragma unroll
    for (int k = 0; k < 4; k++) {
        int it = tid + (k << 8);
        int r = it >> 4, c = it & 15;
        float4 v0 = sv[2 * k], v1 = sv[2 * k + 1];
        uint32_t hw[4], lw[4];
        split2(v0.x, v0.y, hw[0], lw[0]);
        split2(v0.z, v0.w, hw[1], lw[1]);
        split2(v1.x, v1.y, hw[2], lw[2]);
        split2(v1.z, v1.w, hw[3], lw[3]);
        int eo = r * LDS_STRIDE + c * 8;
        *reinterpret_cast<uint4*>(sAh + eo) = make_uint4(hw[0], hw[1], hw[2], hw[3]);
        *reinterpret_cast<uint4*>(sAl + eo) = make_uint4(lw[0], lw[1], lw[2], lw[3]);
    }
}

__global__ __launch_bounds__(256, 1)
void sage_gemm_pers(const float* __restrict__ Ain, const float* __restrict__ Xin,
                    const __nv_bfloat16* __restrict__ wsplit,  // Wl hi,lo | Wr hi,lo
                    const float* __restrict__ bl,
                    const float* __restrict__ res, float* __restrict__ out,
                    __half* __restrict__ h16out, int grid) {
    extern __shared__ __align__(16) char smraw[];
    __nv_bfloat16* sA = reinterpret_cast<__nv_bfloat16*>(smraw + A_BASE_B);
    __shared__ float s_bl[128];

    const int tid  = threadIdx.x;
    const int wid  = tid >> 5;
    const int lane = tid & 31;
    const int g    = lane >> 2;
    const int tg   = lane & 3;
    const int m0w  = (wid & 1) * 32;
    const int n0w  = (wid >> 1) * 32;

    if (tid < 128) s_bl[tid] = __ldg(bl + tid);

    // load all 4 W planes once (8192 x 16B)
    for (int it = tid; it < 8192; it += 256) {
        int p  = it >> 11;
        int rc = it & 2047;
        int r = rc >> 4, c = rc & 15;
        const uint4* src = reinterpret_cast<const uint4*>(wsplit + p * 16384 + r * 128 + c * 8);
        *reinterpret_cast<uint4*>(smraw + p * W_PLANE_B + (r * LDS_STRIDE + c * 8) * 2) = __ldg(src);
    }

    const uint32_t uS  = smem_u32(smraw);
    const uint32_t uA0 = uS + A_BASE_B;
    const uint32_t aoff = (uint32_t)(((lane & 15) * LDS_STRIDE + (lane >> 4) * 8) * 2);
    const uint32_t boff = (uint32_t)((((lane & 7) + ((lane >> 4) << 3)) * LDS_STRIDE
                                      + ((lane >> 3) & 1) * 8) * 2);

    const int bid = blockIdx.x;
    if (bid >= NTILES) return;
    const int ntiles = (NTILES - bid - 1) / grid + 1;
    const int nseq   = 2 * ntiles;

    float4 sv[8];
    float acc[2][4][4];

    ldg_tile(Ain, bid * 64, tid, sv);
    sts_tile(sA, sA + A_PLANE_B / 2, tid, sv);
    __syncthreads();

    int tile = bid;
    for (int i = 0; i < nseq; i++) {
        const int buf  = i & 1;
        const int pass = i & 1;
        const int m0   = tile * 64;

        if (pass == 0) {
#pragma unroll
            for (int mt = 0; mt < 2; mt++)
#pragma unroll
                for (int nt = 0; nt < 4; nt++)
#pragma unroll
                    for (int q = 0; q < 4; q++) acc[mt][nt][q] = 0.f;
        }

        const bool have_next = (i + 1) < nseq;
        if (have_next) {
            int npass = (i + 1) & 1;
            int ntile = npass ? tile : tile + grid;
            ldg_tile(npass ? Xin : Ain, ntile * 64, tid, sv);
        }

        {
            const uint32_t uWh = uS + (uint32_t)pass * 2 * W_PLANE_B;
            const uint32_t uWl = uWh + W_PLANE_B;
            const uint32_t uAh = uA0 + (uint32_t)buf * 2 * A_PLANE_B;
            const uint32_t uAl = uAh + A_PLANE_B;
#pragma unroll
            for (int kk = 0; kk < 8; kk++) {
                const uint32_t kB = kk * 32;
                uint32_t ah[2][4], al[2][4], bh[2][4], blo[2][4];
#pragma unroll
                for (int mt = 0; mt < 2; mt++) {
                    uint32_t rb = (uint32_t)((m0w + mt * 16) * LDS_STRIDE * 2) + kB + aoff;
                    LDMX4(ah[mt], uAh + rb);
                    LDMX4(al[mt], uAl + rb);
                }
#pragma unroll
                for (int p = 0; p < 2; p++) {
                    uint32_t rb = (uint32_t)((n0w + p * 16) * LDS_STRIDE * 2) + kB + boff;
                    LDMX4(bh[p],  uWh + rb);
                    LDMX4(blo[p], uWl + rb);
                }
#pragma unroll
                for (int mt = 0; mt < 2; mt++)
#pragma unroll
                    for (int nt = 0; nt < 4; nt++) {
                        int p = nt >> 1, s = (nt & 1) * 2;
                        mma_bf16(acc[mt][nt], ah[mt], bh[p][s], bh[p][s + 1]);
                        mma_bf16(acc[mt][nt], al[mt], bh[p][s], bh[p][s + 1]);
                        mma_bf16(acc[mt][nt], ah[mt], blo[p][s], blo[p][s + 1]);
                    }
            }
        }

        if (pass == 1) {
#pragma unroll
            for (int mt = 0; mt < 2; mt++) {
#pragma unroll
                for (int half = 0; half < 2; half++) {
                    int m = m0 + m0w + mt * 16 + g + half * 8;
                    if (m < N_NODES) {
#pragma unroll
                        for (int nt = 0; nt < 4; nt++) {
                            int n = n0w + nt * 8 + tg * 2;
                            float2 v;
                            v.x = fmaxf(acc[mt][nt][half * 2 + 0] + s_bl[n], 0.f);
                            v.y = fmaxf(acc[mt][nt][half * 2 + 1] + s_bl[n + 1], 0.f);
                            if (res) {
                                float2 rv = *reinterpret_cast<const float2*>(res + (size_t)m * FEAT + n);
                                v.x += rv.x; v.y += rv.y;
                            }
                            *reinterpret_cast<float2*>(out + (size_t)m * FEAT + n) = v;
                            if (h16out) {
                                __half2 hv = __floats2half2_rn(v.x, v.y);
                                *reinterpret_cast<__half2*>(h16out + (size_t)m * FEAT + n) = hv;
                            }
                        }
                    }
                }
            }
            tile += grid;
        }

        if (have_next) {
            __nv_bfloat16* dAh = sA + (size_t)(buf ^ 1) * A_PLANE_B;
            __nv_bfloat16* dAl = dAh + A_PLANE_B / 2;
            sts_tile(dAh, dAl, tid, sv);
        }
        __syncthreads();
    }
}

// ---------------- classifier: MMA, BM=128, N=40 ----------------
#define SMEM_CLS ((128 + 40) * 2 * LDS_STRIDE * 2)

__global__ __launch_bounds__(256, 2)
void classifier_mma(const float* __restrict__ X,
                    const __nv_bfloat16* __restrict__ wcsplit,
                    const float* __restrict__ bc,
                    float* __restrict__ out) {
    extern __shared__ __align__(16) char smraw[];
    __nv_bfloat16* sAh = reinterpret_cast<__nv_bfloat16*>(smraw);
    __nv_bfloat16* sAl = sAh + 128 * LDS_STRIDE;
    __nv_bfloat16* sWh = sAl + 128 * LDS_STRIDE;
    __nv_bfloat16* sWl = sWh + 40 * LDS_STRIDE;
    __shared__ float s_bc[N_CLS];

    const int tid  = threadIdx.x;
    const int wid  = tid >> 5;
    const int lane = tid & 31;
    const int g    = lane >> 2;
    const int tg   = lane & 3;
    const int m0   = blockIdx.x * 128;

    if (tid < N_CLS) s_bc[tid] = __ldg(bc + tid);

    {
        const __nv_bfloat16* whi = wcsplit;
        const __nv_bfloat16* wlo = wcsplit + 5120;
        for (int it = tid; it < 640; it += 256) {
            int r = it >> 4, c = it & 15;
            int so = r * 128 + c * 8, eo = r * LDS_STRIDE + c * 8;
            *reinterpret_cast<uint4*>(sWh + eo) = __ldg(reinterpret_cast<const uint4*>(whi + so));
            *reinterpret_cast<uint4*>(sWl + eo) = __ldg(reinterpret_cast<const uint4*>(wlo + so));
        }
    }
    for (int it = tid; it < 2048; it += 256) {
        int r = it >> 4, c = it & 15;
        int m = m0 + r;
        float4 v0 = make_float4(0.f, 0.f, 0.f, 0.f), v1 = v0;
        if (m < N_NODES) {
            const float4* gp = reinterpret_cast<const float4*>(X + (size_t)m * FEAT + c * 8);
            v0 = __ldg(gp);
            v1 = __ldg(gp + 1);
        }
        uint32_t hw[4], lw[4];
        split2(v0.x, v0.y, hw[0], lw[0]);
        split2(v0.z, v0.w, hw[1], lw[1]);
        split2(v1.x, v1.y, hw[2], lw[2]);
        split2(v1.z, v1.w, hw[3], lw[3]);
        int eo = r * LDS_STRIDE + c * 8;
        *reinterpret_cast<uint4*>(sAh + eo) = make_uint4(hw[0], hw[1], hw[2], hw[3]);
        *reinterpret_cast<uint4*>(sAl + eo) = make_uint4(lw[0], lw[1], lw[2], lw[3]);
    }
    __syncthreads();

    const uint32_t aoff = (uint32_t)(((lane & 15) * LDS_STRIDE + (lane >> 4) * 8) * 2);
    const uint32_t uAh = smem_u32(sAh), uAl = smem_u32(sAl);
    const uint32_t uWh = smem_u32(sWh), uWl = smem_u32(sWl);

    float acc[5][4];
#pragma unroll
    for (int nt = 0; nt < 5; nt++)
#pragma unroll
        for (int q = 0; q < 4; q++) acc[nt][q] = 0.f;

#pragma unroll
    for (int kk = 0; kk < 8; kk++) {
        const uint32_t kB = kk * 32;
        uint32_t ah[4], al[4], bh[5][2], blo[5][2];
        {
            uint32_t rb = (uint32_t)(wid * 16 * LDS_STRIDE * 2) + kB + aoff;
            LDMX4(ah, uAh + rb);
            LDMX4(al, uAl + rb);
        }
#pragma unroll
        for (int nt = 0; nt < 5; nt++) {
            uint32_t rb = (uint32_t)(((nt * 8 + (lane & 7)) * LDS_STRIDE
                                      + ((lane >> 3) & 1) * 8) * 2) + kB;
            LDMX2(bh[nt],  uWh + rb);
            LDMX2(blo[nt], uWl + rb);
        }
#pragma unroll
        for (int nt = 0; nt < 5; nt++) {
            mma_bf16(acc[nt], ah, bh[nt][0], bh[nt][1]);
            mma_bf16(acc[nt], al, bh[nt][0], bh[nt][1]);
            mma_bf16(acc[nt], ah, blo[nt][0], blo[nt][1]);
        }
    }

#pragma unroll
    for (int half = 0; half < 2; half++) {
        int m = m0 + wid * 16 + g + half * 8;
        if (m < N_NODES) {
#pragma unroll
            for (int nt = 0; nt < 5; nt++) {
                int n = nt * 8 + tg * 2;
                float2 v;
                v.x = acc[nt][half * 2 + 0] + s_bc[n];
                v.y = acc[nt][half * 2 + 1] + s_bc[n + 1];
                *reinterpret_cast<float2*>(out + (size_t)m * N_CLS + n) = v;
            }
        }
    }
}

// ---------------- launch ----------------
extern "C" void kernel_launch(void* const* d_in, const int* in_sizes, int n_in,
                              void* d_out, int out_size) {
    const float* x   = (const float*)d_in[0];
    const int*   ei  = (const int*)d_in[1];
    const float* Wl1 = (const float*)d_in[2];
    const float* bl1 = (const float*)d_in[3];
    const float* Wr1 = (const float*)d_in[4];
    const float* Wl2 = (const float*)d_in[5];
    const float* bl2 = (const float*)d_in[6];
    const float* Wr2 = (const float*)d_in[7];
    const float* Wl3 = (const float*)d_in[8];
    const float* bl3 = (const float*)d_in[9];
    const float* Wr3 = (const float*)d_in[10];
    const float* Wc  = (const float*)d_in[11];
    const float* bc  = (const float*)d_in[12];
    float* out = (float*)d_out;

    const int* src = ei;
    const int* dst = ei + N_EDGES;

    float *p_agg, *p_h1, *p_h2, *p_h3;
    __half* p_h16;
    __nv_bfloat16* p_ws;
    cudaGetSymbolAddress((void**)&p_agg, g_agg);
    cudaGetSymbolAddress((void**)&p_h1,  g_h1);
    cudaGetSymbolAddress((void**)&p_h2,  g_h2);
    cudaGetSymbolAddress((void**)&p_h3,  g_h3);
    cudaGetSymbolAddress((void**)&p_h16, g_h16);
    cudaGetSymbolAddress((void**)&p_ws,  g_wsplit);

    int smcount = 148;
    cudaDeviceGetAttribute(&smcount, cudaDevAttrMultiProcessorCount, 0);
    int pgrid = smcount < NTILES ? smcount : NTILES;

    cudaFuncSetAttribute(sage_gemm_pers, cudaFuncAttributeMaxDynamicSharedMemorySize, SMEM_PERS);
    cudaFuncSetAttribute(classifier_mma, cudaFuncAttributeMaxDynamicSharedMemorySize, SMEM_CLS);
    cudaFuncSetAttribute(scan_all,       cudaFuncAttributeMaxDynamicSharedMemorySize, SMEM_SCAN);

    const int edge_blocks   = (N_EDGES + 255) / 256;
    const int gather_blocks = (N_NODES * 32 + 255) / 256;
    const int cls_blocks    = (N_NODES + 127) / 128;

    // prep + CSR build (4 launches)
    prep_and_zero<<<6850, 256>>>(Wl1, Wr1, Wl2, Wr2, Wl3, Wr3, Wc, x);
    deg_count_i<<<edge_blocks, 256>>>(dst);
    scan_all<<<1, 1024, SMEM_SCAN>>>();
    bucket_edges<<<edge_blocks, 256>>>(src, dst);

    // layer 1 (gather reads x16; epilogue writes h1 + h16<-h1)
    gather_mean<<<gather_blocks, 256>>>(p_h16);
    sage_gemm_pers<<<pgrid, 256, SMEM_PERS>>>(p_agg, x, p_ws + 0 * 65536, bl1, nullptr, p_h1, p_h16, pgrid);

    // layer 2 (gather reads h16=h1; epilogue writes h2 + h16<-h2)
    gather_mean<<<gather_blocks, 256>>>(p_h16);
    sage_gemm_pers<<<pgrid, 256, SMEM_PERS>>>(p_agg, p_h1, p_ws + 1 * 65536, bl2, nullptr, p_h2, p_h16, pgrid);

    // layer 3 + residual (no shadow needed afterwards)
    gather_mean<<<gather_blocks, 256>>>(p_h16);
    sage_gemm_pers<<<pgrid, 256, SMEM_PERS>>>(p_agg, p_h2, p_ws + 2 * 65536, bl3, p_h2, p_h3, nullptr, pgrid);

    // classifier
    classifier_mma<<<cls_blocks, 256, SMEM_CLS>>>(p_h3, p_ws + WC_OFF, bc, out);
}

// round 16
// speedup vs baseline: 1.0691x; 1.0691x over previous
#include <cuda_runtime.h>
#include <cuda_bf16.h>
#include <cstdint>

#define N_NODES 50000
#define N_EDGES 600000
#define FEAT    128
#define N_CLS   40
#define NTILES  782          // ceil(50000/64)

// ---------------- scratch (no allocations allowed) ----------------
__device__ float g_dinv[N_NODES];
__device__ int   g_degi[N_NODES];
__device__ int   g_rowptr[N_NODES];
__device__ int   g_cursor[N_NODES];
__device__ int   g_esrc[N_EDGES];
__device__ __nv_bfloat16 g_aggh[N_NODES * FEAT];   // aggregate, split hi plane
__device__ __nv_bfloat16 g_aggl[N_NODES * FEAT];   // aggregate, split lo plane
__device__ float g_h1[N_NODES * FEAT];
__device__ float g_h2[N_NODES * FEAT];
__device__ float g_h3[N_NODES * FEAT];
// pre-split weights: 6 x [hi 16384 | lo 16384], then Wc [hi 5120 | lo 5120]
#define WC_OFF (6 * 32768)
__device__ __nv_bfloat16 g_wsplit[6 * 32768 + 2 * 5120];

// ---------------- PTX helpers ----------------
__device__ __forceinline__ uint32_t smem_u32(const void* p) {
    uint32_t a;
    asm("{ .reg .u64 t; cvta.to.shared.u64 t, %1; cvt.u32.u64 %0, t; }" : "=r"(a) : "l"(p));
    return a;
}

__device__ __forceinline__ void mma_bf16(float* c, const uint32_t* a, uint32_t b0, uint32_t b1) {
    asm volatile(
        "mma.sync.aligned.m16n8k16.row.col.f32.bf16.bf16.f32 "
        "{%0,%1,%2,%3}, {%4,%5,%6,%7}, {%8,%9}, {%0,%1,%2,%3};"
        : "+f"(c[0]), "+f"(c[1]), "+f"(c[2]), "+f"(c[3])
        : "r"(a[0]), "r"(a[1]), "r"(a[2]), "r"(a[3]), "r"(b0), "r"(b1));
}

#define LDMX4(R, addr) \
    asm volatile("ldmatrix.sync.aligned.m8n8.x4.shared.b16 {%0,%1,%2,%3}, [%4];" \
        : "=r"((R)[0]), "=r"((R)[1]), "=r"((R)[2]), "=r"((R)[3]) : "r"(addr))
#define LDMX2(R, addr) \
    asm volatile("ldmatrix.sync.aligned.m8n8.x2.shared.b16 {%0,%1}, [%2];" \
        : "=r"((R)[0]), "=r"((R)[1]) : "r"(addr))

#define LDS_STRIDE 136   // 272B rows (17 x 16B, odd -> ldmatrix conflict-free)

__device__ __forceinline__ void split2(float f0, float f1, uint32_t& hw, uint32_t& lw) {
    __nv_bfloat16 h0 = __float2bfloat16(f0);
    __nv_bfloat16 h1 = __float2bfloat16(f1);
    __nv_bfloat16 l0 = __float2bfloat16(f0 - __bfloat162float(h0));
    __nv_bfloat16 l1 = __float2bfloat16(f1 - __bfloat162float(h1));
    hw = ((uint32_t)__bfloat16_as_ushort(h1) << 16) | __bfloat16_as_ushort(h0);
    lw = ((uint32_t)__bfloat16_as_ushort(l1) << 16) | __bfloat16_as_ushort(l0);
}

// ---------------- prep: weight split + Wc split + zero degi (one grid) ----------------
__global__ void prep_and_zero(const float* __restrict__ Wl1, const float* __restrict__ Wr1,
                              const float* __restrict__ Wl2, const float* __restrict__ Wr2,
                              const float* __restrict__ Wl3, const float* __restrict__ Wr3,
                              const float* __restrict__ Wc) {
    int b = blockIdx.x;
    if (b < 384) {
        int idx = b * 256 + threadIdx.x;
        int lm = idx / 16384;
        int e  = idx % 16384;
        const float* W;
        switch (lm) {
            case 0: W = Wl1; break;
            case 1: W = Wr1; break;
            case 2: W = Wl2; break;
            case 3: W = Wr2; break;
            case 4: W = Wl3; break;
            default: W = Wr3; break;
        }
        float f = __ldg(W + e);
        __nv_bfloat16 h = __float2bfloat16(f);
        __nv_bfloat16 l = __float2bfloat16(f - __bfloat162float(h));
        __nv_bfloat16* base = g_wsplit + (size_t)lm * 32768;
        base[e]         = h;
        base[16384 + e] = l;
    } else if (b < 404) {
        int e = (b - 384) * 256 + threadIdx.x;
        if (e < 5120) {
            float f = __ldg(Wc + e);
            __nv_bfloat16 h = __float2bfloat16(f);
            __nv_bfloat16 l = __float2bfloat16(f - __bfloat162float(h));
            g_wsplit[WC_OFF + e]        = h;
            g_wsplit[WC_OFF + 5120 + e] = l;
        }
    } else {
        int i = (b - 404) * 256 + threadIdx.x;
        if (i < N_NODES) g_degi[i] = 0;
    }
}

// ---------------- degree count ----------------
__global__ void deg_count_i(const int* __restrict__ dst) {
    int e = blockIdx.x * blockDim.x + threadIdx.x;
    if (e < N_EDGES) atomicAdd(&g_degi[dst[e]], 1);
}

// ---------------- single-kernel scan via smem staging ----------------
#define SCAN_R     1568
#define SMEM_SCAN  (32 * SCAN_R * 4)

__global__ __launch_bounds__(1024)
void scan_all() {
    extern __shared__ int sdeg[];
    __shared__ int woff[32];
    const int t = threadIdx.x, lane = t & 31, w = t >> 5;
    const int base = w * SCAN_R;

    for (int i = t; i < 32 * SCAN_R; i += 1024)
        sdeg[i] = (i < N_NODES) ? g_degi[i] : 0;
    __syncthreads();

    int sum = 0;
    for (int i = lane; i < SCAN_R; i += 32) sum += sdeg[base + i];
#pragma unroll
    for (int d = 16; d; d >>= 1) sum += __shfl_down_sync(0xffffffffu, sum, d);
    if (lane == 0) woff[w] = sum;
    __syncthreads();
    if (w == 0) {
        int v = woff[lane];
        int inc = v;
#pragma unroll
        for (int d = 1; d < 32; d <<= 1) {
            int u = __shfl_up_sync(0xffffffffu, inc, d);
            if (lane >= d) inc += u;
        }
        woff[lane] = inc - v;
    }
    __syncthreads();

    int run = woff[w];
    for (int c = 0; c < SCAN_R; c += 32) {
        int idx = base + c + lane;
        int v = sdeg[idx];
        int inc = v;
#pragma unroll
        for (int d = 1; d < 32; d <<= 1) {
            int u = __shfl_up_sync(0xffffffffu, inc, d);
            if (lane >= d) inc += u;
        }
        if (idx < N_NODES) {
            int excl = run + inc - v;
            g_rowptr[idx] = excl;
            g_cursor[idx] = excl;
            g_dinv[idx]   = 1.0f / fmaxf((float)v, 1.0f);
        }
        run += __shfl_sync(0xffffffffu, inc, 31);
    }
}

__global__ void bucket_edges(const int* __restrict__ src, const int* __restrict__ dst) {
    int e = blockIdx.x * blockDim.x + threadIdx.x;
    if (e < N_EDGES) {
        int d = dst[e];
        int pos = atomicAdd(&g_cursor[d], 1);
        g_esrc[pos] = src[e];
    }
}

// ---------------- CSR mean-gather: one warp per node, writes split bf16 planes ----------------
__global__ __launch_bounds__(256)
void gather_mean(const float* __restrict__ X) {
    int wid  = (blockIdx.x * blockDim.x + threadIdx.x) >> 5;
    int lane = threadIdx.x & 31;
    if (wid >= N_NODES) return;
    int start = g_rowptr[wid];
    int deg   = g_degi[wid];
    float4 acc = make_float4(0.f, 0.f, 0.f, 0.f);
    int j = 0;
    for (; j + 4 <= deg; j += 4) {
        int s0 = __ldg(g_esrc + start + j);
        int s1 = __ldg(g_esrc + start + j + 1);
        int s2 = __ldg(g_esrc + start + j + 2);
        int s3 = __ldg(g_esrc + start + j + 3);
        float4 v0 = __ldg(reinterpret_cast<const float4*>(X + (size_t)s0 * FEAT) + lane);
        float4 v1 = __ldg(reinterpret_cast<const float4*>(X + (size_t)s1 * FEAT) + lane);
        float4 v2 = __ldg(reinterpret_cast<const float4*>(X + (size_t)s2 * FEAT) + lane);
        float4 v3 = __ldg(reinterpret_cast<const float4*>(X + (size_t)s3 * FEAT) + lane);
        acc.x += v0.x + v1.x + v2.x + v3.x;
        acc.y += v0.y + v1.y + v2.y + v3.y;
        acc.z += v0.z + v1.z + v2.z + v3.z;
        acc.w += v0.w + v1.w + v2.w + v3.w;
    }
    for (; j < deg; j++) {
        int s = __ldg(g_esrc + start + j);
        float4 v = __ldg(reinterpret_cast<const float4*>(X + (size_t)s * FEAT) + lane);
        acc.x += v.x; acc.y += v.y; acc.z += v.z; acc.w += v.w;
    }
    float di = g_dinv[wid];
    acc.x *= di; acc.y *= di; acc.z *= di; acc.w *= di;
    uint32_t h0, l0, h1, l1;
    split2(acc.x, acc.y, h0, l0);
    split2(acc.z, acc.w, h1, l1);
    size_t off = (size_t)wid * FEAT + lane * 4;
    *reinterpret_cast<uint2*>(g_aggh + off) = make_uint2(h0, h1);
    *reinterpret_cast<uint2*>(g_aggl + off) = make_uint2(l0, l1);
}

// ---------------- persistent SAGE GEMM (R10 structure, pre-split agg input) ----------------
#define W_PLANE_B  34816
#define A_PLANE_B  17408
#define A_BASE_B   139264
#define SMEM_PERS  208896

// pass-0 (agg): pure bf16 copy, 4 chunks/thread, sv = 4x(hi uint4) + 4x(lo uint4)
__device__ __forceinline__ void ldg_tile_agg(const __nv_bfloat16* __restrict__ Hh,
                                             const __nv_bfloat16* __restrict__ Hl,
                                             int m0, int tid, uint4* sv) {
#pragma unroll
    for (int k = 0; k < 4; k++) {
        int it = tid + (k << 8);
        int r = it >> 4, c = it & 15;
        int m = m0 + r;
        uint4 z = make_uint4(0u, 0u, 0u, 0u);
        if (m < N_NODES) {
            size_t off = (size_t)m * FEAT + c * 8;
            sv[2 * k]     = __ldg(reinterpret_cast<const uint4*>(Hh + off));
            sv[2 * k + 1] = __ldg(reinterpret_cast<const uint4*>(Hl + off));
        } else {
            sv[2 * k] = z;
            sv[2 * k + 1] = z;
        }
    }
}

__device__ __forceinline__ void sts_tile_agg(__nv_bfloat16* __restrict__ sAh,
                                             __nv_bfloat16* __restrict__ sAl,
                                             int tid, const uint4* sv) {
#pragma unroll
    for (int k = 0; k < 4; k++) {
        int it = tid + (k << 8);
        int r = it >> 4, c = it & 15;
        int eo = r * LDS_STRIDE + c * 8;
        *reinterpret_cast<uint4*>(sAh + eo) = sv[2 * k];
        *reinterpret_cast<uint4*>(sAl + eo) = sv[2 * k + 1];
    }
}

// pass-1 (X): fp32 load + split (R10)
__device__ __forceinline__ void ldg_tile_x(const float* __restrict__ A, int m0, int tid,
                                           float4* sv) {
#pragma unroll
    for (int k = 0; k < 4; k++) {
        int it = tid + (k << 8);
        int r = it >> 4, c = it & 15;
        int m = m0 + r;
        float4 z = make_float4(0.f, 0.f, 0.f, 0.f);
        if (m < N_NODES) {
            const float4* gp = reinterpret_cast<const float4*>(A + (size_t)m * FEAT + c * 8);
            sv[2 * k]     = __ldg(gp);
            sv[2 * k + 1] = __ldg(gp + 1);
        } else {
            sv[2 * k] = z;
            sv[2 * k + 1] = z;
        }
    }
}

__device__ __forceinline__ void sts_tile_x(__nv_bfloat16* __restrict__ sAh,
                                           __nv_bfloat16* __restrict__ sAl,
                                           int tid, const float4* sv) {
#pragma unroll
    for (int k = 0; k < 4; k++) {
        int it = tid + (k << 8);
        int r = it >> 4, c = it & 15;
        float4 v0 = sv[2 * k], v1 = sv[2 * k + 1];
        uint32_t hw[4], lw[4];
        split2(v0.x, v0.y, hw[0], lw[0]);
        split2(v0.z, v0.w, hw[1], lw[1]);
        split2(v1.x, v1.y, hw[2], lw[2]);
        split2(v1.z, v1.w, hw[3], lw[3]);
        int eo = r * LDS_STRIDE + c * 8;
        *reinterpret_cast<uint4*>(sAh + eo) = make_uint4(hw[0], hw[1], hw[2], hw[3]);
        *reinterpret_cast<uint4*>(sAl + eo) = make_uint4(lw[0], lw[1], lw[2], lw[3]);
    }
}

__global__ __launch_bounds__(256, 1)
void sage_gemm_pers(const __nv_bfloat16* __restrict__ Ah, const __nv_bfloat16* __restrict__ Al,
                    const float* __restrict__ Xin,
                    const __nv_bfloat16* __restrict__ wsplit,  // Wl hi,lo | Wr hi,lo
                    const float* __restrict__ bl,
                    const float* __restrict__ res, float* __restrict__ out,
                    int grid) {
    extern __shared__ __align__(16) char smraw[];
    __nv_bfloat16* sA = reinterpret_cast<__nv_bfloat16*>(smraw + A_BASE_B);
    __shared__ float s_bl[128];

    const int tid  = threadIdx.x;
    const int wid  = tid >> 5;
    const int lane = tid & 31;
    const int g    = lane >> 2;
    const int tg   = lane & 3;
    const int m0w  = (wid & 1) * 32;
    const int n0w  = (wid >> 1) * 32;

    if (tid < 128) s_bl[tid] = __ldg(bl + tid);

    // load all 4 W planes once (8192 x 16B)
    for (int it = tid; it < 8192; it += 256) {
        int p  = it >> 11;
        int rc = it & 2047;
        int r = rc >> 4, c = rc & 15;
        const uint4* src = reinterpret_cast<const uint4*>(wsplit + p * 16384 + r * 128 + c * 8);
        *reinterpret_cast<uint4*>(smraw + p * W_PLANE_B + (r * LDS_STRIDE + c * 8) * 2) = __ldg(src);
    }

    const uint32_t uS  = smem_u32(smraw);
    const uint32_t uA0 = uS + A_BASE_B;
    const uint32_t aoff = (uint32_t)(((lane & 15) * LDS_STRIDE + (lane >> 4) * 8) * 2);
    const uint32_t boff = (uint32_t)((((lane & 7) + ((lane >> 4) << 3)) * LDS_STRIDE
                                      + ((lane >> 3) & 1) * 8) * 2);

    const int bid = blockIdx.x;
    if (bid >= NTILES) return;
    const int ntiles = (NTILES - bid - 1) / grid + 1;
    const int nseq   = 2 * ntiles;

    uint4 sv[8];   // holds either 8 x uint4 (agg planes) or 8 x float4 (X) bit-compatible
    float acc[2][4][4];

    ldg_tile_agg(Ah, Al, bid * 64, tid, sv);
    sts_tile_agg(sA, sA + A_PLANE_B / 2, tid, sv);
    __syncthreads();

    int tile = bid;
    for (int i = 0; i < nseq; i++) {
        const int buf  = i & 1;
        const int pass = i & 1;
        const int m0   = tile * 64;

        if (pass == 0) {
#pragma unroll
            for (int mt = 0; mt < 2; mt++)
#pragma unroll
                for (int nt = 0; nt < 4; nt++)
#pragma unroll
                    for (int q = 0; q < 4; q++) acc[mt][nt][q] = 0.f;
        }

        const bool have_next = (i + 1) < nseq;
        int npass = 0;
        if (have_next) {
            npass = (i + 1) & 1;
            int ntile = npass ? tile : tile + grid;
            if (npass)
                ldg_tile_x(Xin, ntile * 64, tid, reinterpret_cast<float4*>(sv));
            else
                ldg_tile_agg(Ah, Al, ntile * 64, tid, sv);
        }

        {
            const uint32_t uWh = uS + (uint32_t)pass * 2 * W_PLANE_B;
            const uint32_t uWl = uWh + W_PLANE_B;
            const uint32_t uAh = uA0 + (uint32_t)buf * 2 * A_PLANE_B;
            const uint32_t uAl = uAh + A_PLANE_B;
#pragma unroll
            for (int kk = 0; kk < 8; kk++) {
                const uint32_t kB = kk * 32;
                uint32_t ah[2][4], al[2][4], bh[2][4], blo[2][4];
#pragma unroll
                for (int mt = 0; mt < 2; mt++) {
                    uint32_t rb = (uint32_t)((m0w + mt * 16) * LDS_STRIDE * 2) + kB + aoff;
                    LDMX4(ah[mt], uAh + rb);
                    LDMX4(al[mt], uAl + rb);
                }
#pragma unroll
                for (int p = 0; p < 2; p++) {
                    uint32_t rb = (uint32_t)((n0w + p * 16) * LDS_STRIDE * 2) + kB + boff;
                    LDMX4(bh[p],  uWh + rb);
                    LDMX4(blo[p], uWl + rb);
                }
#pragma unroll
                for (int mt = 0; mt < 2; mt++)
#pragma unroll
                    for (int nt = 0; nt < 4; nt++) {
                        int p = nt >> 1, s = (nt & 1) * 2;
                        mma_bf16(acc[mt][nt], ah[mt], bh[p][s], bh[p][s + 1]);
                        mma_bf16(acc[mt][nt], al[mt], bh[p][s], bh[p][s + 1]);
                        mma_bf16(acc[mt][nt], ah[mt], blo[p][s], blo[p][s + 1]);
                    }
            }
        }

        if (pass == 1) {
#pragma unroll
            for (int mt = 0; mt < 2; mt++) {
#pragma unroll
                for (int half = 0; half < 2; half++) {
                    int m = m0 + m0w + mt * 16 + g + half * 8;
                    if (m < N_NODES) {
#pragma unroll
                        for (int nt = 0; nt < 4; nt++) {
                            int n = n0w + nt * 8 + tg * 2;
                            float2 v;
                            v.x = fmaxf(acc[mt][nt][half * 2 + 0] + s_bl[n], 0.f);
                            v.y = fmaxf(acc[mt][nt][half * 2 + 1] + s_bl[n + 1], 0.f);
                            if (res) {
                                float2 rv = *reinterpret_cast<const float2*>(res + (size_t)m * FEAT + n);
                                v.x += rv.x; v.y += rv.y;
                            }
                            *reinterpret_cast<float2*>(out + (size_t)m * FEAT + n) = v;
                        }
                    }
                }
            }
            tile += grid;
        }

        if (have_next) {
            __nv_bfloat16* dAh = sA + (size_t)(buf ^ 1) * A_PLANE_B;
            __nv_bfloat16* dAl = dAh + A_PLANE_B / 2;
            if (npass)
                sts_tile_x(dAh, dAl, tid, reinterpret_cast<const float4*>(sv));
            else
                sts_tile_agg(dAh, dAl, tid, sv);
        }
        __syncthreads();
    }
}

// ---------------- classifier: MMA, BM=128, N=40 ----------------
#define SMEM_CLS ((128 + 40) * 2 * LDS_STRIDE * 2)

__global__ __launch_bounds__(256, 2)
void classifier_mma(const float* __restrict__ X,
                    const __nv_bfloat16* __restrict__ wcsplit,
                    const float* __restrict__ bc,
                    float* __restrict__ out) {
    extern __shared__ __align__(16) char smraw[];
    __nv_bfloat16* sAh = reinterpret_cast<__nv_bfloat16*>(smraw);
    __nv_bfloat16* sAl = sAh + 128 * LDS_STRIDE;
    __nv_bfloat16* sWh = sAl + 128 * LDS_STRIDE;
    __nv_bfloat16* sWl = sWh + 40 * LDS_STRIDE;
    __shared__ float s_bc[N_CLS];

    const int tid  = threadIdx.x;
    const int wid  = tid >> 5;
    const int lane = tid & 31;
    const int g    = lane >> 2;
    const int tg   = lane & 3;
    const int m0   = blockIdx.x * 128;

    if (tid < N_CLS) s_bc[tid] = __ldg(bc + tid);

    {
        const __nv_bfloat16* whi = wcsplit;
        const __nv_bfloat16* wlo = wcsplit + 5120;
        for (int it = tid; it < 640; it += 256) {
            int r = it >> 4, c = it & 15;
            int so = r * 128 + c * 8, eo = r * LDS_STRIDE + c * 8;
            *reinterpret_cast<uint4*>(sWh + eo) = __ldg(reinterpret_cast<const uint4*>(whi + so));
            *reinterpret_cast<uint4*>(sWl + eo) = __ldg(reinterpret_cast<const uint4*>(wlo + so));
        }
    }
    for (int it = tid; it < 2048; it += 256) {
        int r = it >> 4, c = it & 15;
        int m = m0 + r;
        float4 v0 = make_float4(0.f, 0.f, 0.f, 0.f), v1 = v0;
        if (m < N_NODES) {
            const float4* gp = reinterpret_cast<const float4*>(X + (size_t)m * FEAT + c * 8);
            v0 = __ldg(gp);
            v1 = __ldg(gp + 1);
        }
        uint32_t hw[4], lw[4];
        split2(v0.x, v0.y, hw[0], lw[0]);
        split2(v0.z, v0.w, hw[1], lw[1]);
        split2(v1.x, v1.y, hw[2], lw[2]);
        split2(v1.z, v1.w, hw[3], lw[3]);
        int eo = r * LDS_STRIDE + c * 8;
        *reinterpret_cast<uint4*>(sAh + eo) = make_uint4(hw[0], hw[1], hw[2], hw[3]);
        *reinterpret_cast<uint4*>(sAl + eo) = make_uint4(lw[0], lw[1], lw[2], lw[3]);
    }
    __syncthreads();

    const uint32_t aoff = (uint32_t)(((lane & 15) * LDS_STRIDE + (lane >> 4) * 8) * 2);
    const uint32_t uAh = smem_u32(sAh), uAl = smem_u32(sAl);
    const uint32_t uWh = smem_u32(sWh), uWl = smem_u32(sWl);

    float acc[5][4];
#pragma unroll
    for (int nt = 0; nt < 5; nt++)
#pragma unroll
        for (int q = 0; q < 4; q++) acc[nt][q] = 0.f;

#pragma unroll
    for (int kk = 0; kk < 8; kk++) {
        const uint32_t kB = kk * 32;
        uint32_t ah[4], al[4], bh[5][2], blo[5][2];
        {
            uint32_t rb = (uint32_t)(wid * 16 * LDS_STRIDE * 2) + kB + aoff;
            LDMX4(ah, uAh + rb);
            LDMX4(al, uAl + rb);
        }
#pragma unroll
        for (int nt = 0; nt < 5; nt++) {
            uint32_t rb = (uint32_t)(((nt * 8 + (lane & 7)) * LDS_STRIDE
                                      + ((lane >> 3) & 1) * 8) * 2) + kB;
            LDMX2(bh[nt],  uWh + rb);
            LDMX2(blo[nt], uWl + rb);
        }
#pragma unroll
        for (int nt = 0; nt < 5; nt++) {
            mma_bf16(acc[nt], ah, bh[nt][0], bh[nt][1]);
            mma_bf16(acc[nt], al, bh[nt][0], bh[nt][1]);
            mma_bf16(acc[nt], ah, blo[nt][0], blo[nt][1]);
        }
    }

#pragma unroll
    for (int half = 0; half < 2; half++) {
        int m = m0 + wid * 16 + g + half * 8;
        if (m < N_NODES) {
#pragma unroll
            for (int nt = 0; nt < 5; nt++) {
                int n = nt * 8 + tg * 2;
                float2 v;
                v.x = acc[nt][half * 2 + 0] + s_bc[n];
                v.y = acc[nt][half * 2 + 1] + s_bc[n + 1];
                *reinterpret_cast<float2*>(out + (size_t)m * N_CLS + n) = v;
            }
        }
    }
}

// ---------------- launch ----------------
extern "C" void kernel_launch(void* const* d_in, const int* in_sizes, int n_in,
                              void* d_out, int out_size) {
    const float* x   = (const float*)d_in[0];
    const int*   ei  = (const int*)d_in[1];
    const float* Wl1 = (const float*)d_in[2];
    const float* bl1 = (const float*)d_in[3];
    const float* Wr1 = (const float*)d_in[4];
    const float* Wl2 = (const float*)d_in[5];
    const float* bl2 = (const float*)d_in[6];
    const float* Wr2 = (const float*)d_in[7];
    const float* Wl3 = (const float*)d_in[8];
    const float* bl3 = (const float*)d_in[9];
    const float* Wr3 = (const float*)d_in[10];
    const float* Wc  = (const float*)d_in[11];
    const float* bc  = (const float*)d_in[12];
    float* out = (float*)d_out;

    const int* src = ei;
    const int* dst = ei + N_EDGES;

    float *p_h1, *p_h2, *p_h3;
    __nv_bfloat16 *p_ws, *p_ah, *p_al;
    cudaGetSymbolAddress((void**)&p_h1, g_h1);
    cudaGetSymbolAddress((void**)&p_h2, g_h2);
    cudaGetSymbolAddress((void**)&p_h3, g_h3);
    cudaGetSymbolAddress((void**)&p_ws, g_wsplit);
    cudaGetSymbolAddress((void**)&p_ah, g_aggh);
    cudaGetSymbolAddress((void**)&p_al, g_aggl);

    int smcount = 148;
    cudaDeviceGetAttribute(&smcount, cudaDevAttrMultiProcessorCount, 0);
    int pgrid = smcount < NTILES ? smcount : NTILES;

    cudaFuncSetAttribute(sage_gemm_pers, cudaFuncAttributeMaxDynamicSharedMemorySize, SMEM_PERS);
    cudaFuncSetAttribute(classifier_mma, cudaFuncAttributeMaxDynamicSharedMemorySize, SMEM_CLS);
    cudaFuncSetAttribute(scan_all,       cudaFuncAttributeMaxDynamicSharedMemorySize, SMEM_SCAN);

    const int edge_blocks   = (N_EDGES + 255) / 256;
    const int gather_blocks = (N_NODES * 32 + 255) / 256;
    const int cls_blocks    = (N_NODES + 127) / 128;

    // prep + CSR build (4 launches, R10 structure)
    prep_and_zero<<<600, 256>>>(Wl1, Wr1, Wl2, Wr2, Wl3, Wr3, Wc);
    deg_count_i<<<edge_blocks, 256>>>(dst);
    scan_all<<<1, 1024, SMEM_SCAN>>>();
    bucket_edges<<<edge_blocks, 256>>>(src, dst);

    // layer 1
    gather_mean<<<gather_blocks, 256>>>(x);
    sage_gemm_pers<<<pgrid, 256, SMEM_PERS>>>(p_ah, p_al, x, p_ws + 0 * 65536, bl1, nullptr, p_h1, pgrid);

    // layer 2
    gather_mean<<<gather_blocks, 256>>>(p_h1);
    sage_gemm_pers<<<pgrid, 256, SMEM_PERS>>>(p_ah, p_al, p_h1, p_ws + 1 * 65536, bl2, nullptr, p_h2, pgrid);

    // layer 3 + residual
    gather_mean<<<gather_blocks, 256>>>(p_h2);
    sage_gemm_pers<<<pgrid, 256, SMEM_PERS>>>(p_ah, p_al, p_h2, p_ws + 2 * 65536, bl3, p_h2, p_h3, pgrid);

    // classifier
    classifier_mma<<<cls_blocks, 256, SMEM_CLS>>>(p_h3, p_ws + WC_OFF, bc, out);
}